// round 2
// baseline (speedup 1.0000x reference)
#include <cuda_runtime.h>
#include <cstdint>

#define NU 100000
#define NS 50000
#define NE 600000
#define DIN 128
#define H1 128
#define H2 64

// ---------------- scratch (device globals; no allocations allowed) ----------
__device__ float g_agg_user[NU * DIN];   // aggregated (summed) src feats per user
__device__ float g_agg_song[NS * DIN];
__device__ float g_h_user[NU * H1];
__device__ float g_h_song[NS * H1];
__device__ float g_cnt_user[NU];
__device__ float g_cnt_song[NS];

// ---------------- small helpers --------------------------------------------
__device__ __forceinline__ unsigned long long pack2(float lo, float hi) {
    unsigned long long r;
    asm("mov.b64 %0, {%1, %2};" : "=l"(r) : "f"(lo), "f"(hi));
    return r;
}
__device__ __forceinline__ void unpack2(unsigned long long v, float& lo, float& hi) {
    asm("mov.b64 {%0, %1}, %2;" : "=f"(lo), "=f"(hi) : "l"(v));
}
__device__ __forceinline__ unsigned long long ffma2(unsigned long long a,
                                                    unsigned long long b,
                                                    unsigned long long c) {
    unsigned long long d;
    asm("fma.rn.f32x2 %0, %1, %2, %3;" : "=l"(d) : "l"(a), "l"(b), "l"(c));
    return d;
}

// ---------------- zero kernel ----------------------------------------------
__global__ void zero_kernel(float4* p, int n4) {
    int i = blockIdx.x * blockDim.x + threadIdx.x;
    if (i < n4) p[i] = make_float4(0.f, 0.f, 0.f, 0.f);
}

// ---------------- degree counts --------------------------------------------
__global__ void count_kernel(const int* __restrict__ us_dst,
                             const int* __restrict__ su_dst,
                             float* __restrict__ cnt_song,
                             float* __restrict__ cnt_user, int n) {
    int i = blockIdx.x * blockDim.x + threadIdx.x;
    if (i < n) {
        atomicAdd(&cnt_song[us_dst[i]], 1.0f);
        atomicAdd(&cnt_user[su_dst[i]], 1.0f);
    }
}

// ---------------- edge scatter-add (1 warp per edge, float4 atomics) -------
__global__ void scatter_kernel(const float* __restrict__ feat,
                               const int* __restrict__ src,
                               const int* __restrict__ dst,
                               float* __restrict__ agg, int n) {
    int e = blockIdx.x * 8 + (threadIdx.x >> 5);
    if (e >= n) return;
    int lane = threadIdx.x & 31;
    int s = src[e];
    int d = dst[e];
    const float4 v =
        *reinterpret_cast<const float4*>(feat + (size_t)s * DIN + lane * 4);
#if __CUDA_ARCH__ >= 900
    atomicAdd(reinterpret_cast<float4*>(agg + (size_t)d * DIN + lane * 4), v);
#else
    float* a = agg + (size_t)d * DIN + lane * 4;
    atomicAdd(a + 0, v.x);
    atomicAdd(a + 1, v.y);
    atomicAdd(a + 2, v.z);
    atomicAdd(a + 3, v.w);
#endif
}

// ---------------- fused SAGE GEMM ------------------------------------------
// out[r, :] = relu?( xdst[r,:] @ Ws + (agg[r,:]/max(cnt[r],1)) @ Wn + bias )
// K = 128 for both operands. W layout: [128, NOUT] row-major.
// BM=64 rows per block, 256 threads, f32x2 packed math (row pairs in lanes).
template <int NOUT>
__global__ void __launch_bounds__(256) sage_gemm(
    const float* __restrict__ xdst, const float* __restrict__ agg,
    const float* __restrict__ cnt, const float* __restrict__ Ws,
    const float* __restrict__ Wn, const float* __restrict__ bias,
    float* __restrict__ out, int M, int do_relu) {
    constexpr int BM = 64;
    constexpr int BK = 16;
    constexpr int CG = NOUT / 4;   // column groups (4 cols each)
    constexpr int RG = 256 / CG;   // row groups
    constexpr int TM = BM / RG;    // rows per thread
    constexpr int NP = TM / 2;     // row pairs per thread
    constexpr int XS = BM + 2;     // sX row stride (66) -> conflict-free

    __shared__ __align__(16) float sW[BK][NOUT];
    __shared__ __align__(16) float sX[BK][XS];
    __shared__ float sinv[BM];

    const int tid = threadIdx.x;
    const int row0 = blockIdx.x * BM;

    if (tid < BM) {
        int r = row0 + tid;
        sinv[tid] = (r < M) ? 1.0f / fmaxf(cnt[r], 1.0f) : 0.0f;
    }

    unsigned long long acc[NP][4];
#pragma unroll
    for (int i = 0; i < NP; i++)
#pragma unroll
        for (int j = 0; j < 4; j++) acc[i][j] = 0ull;

    const int cg = tid % CG;
    const int rg = tid / CG;
    const int n0 = cg * 4;
    const int r0 = rg * TM;

    for (int chunk = 0; chunk < 16; ++chunk) {
        const bool neigh = (chunk >= 8);
        const int kbase = (chunk & 7) * BK;
        const float* Wp = neigh ? Wn : Ws;
        const float* Xp = neigh ? agg : xdst;

        __syncthreads();
        // load W chunk [BK x NOUT]
#pragma unroll
        for (int i = 0; i < (BK * NOUT) / 256; i++) {
            int idx = tid + i * 256;
            int k = idx / NOUT, n = idx % NOUT;
            sW[k][n] = Wp[(kbase + k) * NOUT + n];
        }
        // load X chunk [BM x BK] transposed into sX[k][r]
#pragma unroll
        for (int i = 0; i < (BM * BK) / 256; i++) {
            int idx = tid + i * 256;
            int r = idx / BK, k = idx % BK;
            int gr = row0 + r;
            float v = (gr < M) ? Xp[(size_t)gr * DIN + kbase + k] : 0.0f;
            if (neigh) v *= sinv[r];
            sX[k][r] = v;
        }
        __syncthreads();

#pragma unroll
        for (int k = 0; k < BK; k++) {
            float4 w = *reinterpret_cast<const float4*>(&sW[k][n0]);
            unsigned long long wd0 = pack2(w.x, w.x);
            unsigned long long wd1 = pack2(w.y, w.y);
            unsigned long long wd2 = pack2(w.z, w.z);
            unsigned long long wd3 = pack2(w.w, w.w);
#pragma unroll
            for (int i = 0; i < NP; i++) {
                unsigned long long xp =
                    *reinterpret_cast<const unsigned long long*>(
                        &sX[k][r0 + 2 * i]);
                acc[i][0] = ffma2(xp, wd0, acc[i][0]);
                acc[i][1] = ffma2(xp, wd1, acc[i][1]);
                acc[i][2] = ffma2(xp, wd2, acc[i][2]);
                acc[i][3] = ffma2(xp, wd3, acc[i][3]);
            }
        }
    }

    // epilogue: bias (+relu), unpack row pairs, store
    const float4 bvec = *reinterpret_cast<const float4*>(&bias[n0]);
#pragma unroll
    for (int i = 0; i < NP; i++) {
        float la[4], lb[4];
#pragma unroll
        for (int j = 0; j < 4; j++) unpack2(acc[i][j], la[j], lb[j]);
        la[0] += bvec.x; la[1] += bvec.y; la[2] += bvec.z; la[3] += bvec.w;
        lb[0] += bvec.x; lb[1] += bvec.y; lb[2] += bvec.z; lb[3] += bvec.w;
        if (do_relu) {
#pragma unroll
            for (int j = 0; j < 4; j++) {
                la[j] = fmaxf(la[j], 0.0f);
                lb[j] = fmaxf(lb[j], 0.0f);
            }
        }
        int ra = row0 + r0 + 2 * i;
        int rb = ra + 1;
        if (ra < M)
            *reinterpret_cast<float4*>(out + (size_t)ra * NOUT + n0) =
                make_float4(la[0], la[1], la[2], la[3]);
        if (rb < M)
            *reinterpret_cast<float4*>(out + (size_t)rb * NOUT + n0) =
                make_float4(lb[0], lb[1], lb[2], lb[3]);
    }
}

// ---------------- host launch ----------------------------------------------
static inline void zero_buf(float* p, int nfloats) {
    int n4 = nfloats / 4;
    zero_kernel<<<(n4 + 255) / 256, 256>>>(reinterpret_cast<float4*>(p), n4);
}

extern "C" void kernel_launch(void* const* d_in, const int* in_sizes, int n_in,
                              void* d_out, int out_size) {
    const float* x_user = (const float*)d_in[0];
    const float* x_song = (const float*)d_in[1];
    const int* us_src = (const int*)d_in[2];
    const int* us_dst = (const int*)d_in[3];
    const int* su_src = (const int*)d_in[4];
    const int* su_dst = (const int*)d_in[5];
    const float* W1_us_n = (const float*)d_in[6];
    const float* W1_us_s = (const float*)d_in[7];
    const float* b1_us = (const float*)d_in[8];
    const float* W1_su_n = (const float*)d_in[9];
    const float* W1_su_s = (const float*)d_in[10];
    const float* b1_su = (const float*)d_in[11];
    const float* W2_us_n = (const float*)d_in[12];
    const float* W2_us_s = (const float*)d_in[13];
    const float* b2_us = (const float*)d_in[14];
    const float* W2_su_n = (const float*)d_in[15];
    const float* W2_su_s = (const float*)d_in[16];
    const float* b2_su = (const float*)d_in[17];
    float* out = (float*)d_out;

    float *agg_user, *agg_song, *h_user, *h_song, *cnt_user, *cnt_song;
    cudaGetSymbolAddress((void**)&agg_user, g_agg_user);
    cudaGetSymbolAddress((void**)&agg_song, g_agg_song);
    cudaGetSymbolAddress((void**)&h_user, g_h_user);
    cudaGetSymbolAddress((void**)&h_song, g_h_song);
    cudaGetSymbolAddress((void**)&cnt_user, g_cnt_user);
    cudaGetSymbolAddress((void**)&cnt_song, g_cnt_song);

    const int scatter_blocks = (NE + 7) / 8;

    // ---- zero aggregation buffers + counts
    zero_buf(agg_user, NU * DIN);
    zero_buf(agg_song, NS * DIN);
    zero_buf(cnt_user, NU);
    zero_buf(cnt_song, NS);

    // ---- in-degree counts (shared by both layers)
    count_kernel<<<(NE + 255) / 256, 256>>>(us_dst, su_dst, cnt_song, cnt_user,
                                            NE);

    // ---- layer 1 aggregation
    scatter_kernel<<<scatter_blocks, 256>>>(x_user, us_src, us_dst, agg_song,
                                            NE);
    scatter_kernel<<<scatter_blocks, 256>>>(x_song, su_src, su_dst, agg_user,
                                            NE);

    // ---- layer 1 GEMMs (+bias +relu)
    sage_gemm<H1><<<(NS + 63) / 64, 256>>>(x_song, agg_song, cnt_song, W1_us_s,
                                           W1_us_n, b1_us, h_song, NS, 1);
    sage_gemm<H1><<<(NU + 63) / 64, 256>>>(x_user, agg_user, cnt_user, W1_su_s,
                                           W1_su_n, b1_su, h_user, NU, 1);

    // ---- layer 2 aggregation
    zero_buf(agg_user, NU * DIN);
    zero_buf(agg_song, NS * DIN);
    scatter_kernel<<<scatter_blocks, 256>>>(h_user, us_src, us_dst, agg_song,
                                            NE);
    scatter_kernel<<<scatter_blocks, 256>>>(h_song, su_src, su_dst, agg_user,
                                            NE);

    // ---- layer 2 GEMMs (+bias), writing directly into concat output:
    // rows [0, NU)        = out_user
    // rows [NU, NU+NS)    = out_song
    sage_gemm<H2><<<(NS + 63) / 64, 256>>>(h_song, agg_song, cnt_song, W2_us_s,
                                           W2_us_n, b2_us, out + (size_t)NU * H2,
                                           NS, 0);
    sage_gemm<H2><<<(NU + 63) / 64, 256>>>(h_user, agg_user, cnt_user, W2_su_s,
                                           W2_su_n, b2_su, out, NU, 0);
}

// round 3
// speedup vs baseline: 1.2113x; 1.2113x over previous
#include <cuda_runtime.h>
#include <cstdint>

#define NU 100000
#define NS 50000
#define NE 600000
#define DIN 128
#define H1 128
#define H2 64

// ---------------- scratch (device globals; no allocations allowed) ----------
__device__ float g_mean_user[NU * DIN];
__device__ float g_mean_song[NS * DIN];
__device__ float g_h_user[NU * H1];
__device__ float g_h_song[NS * H1];
__device__ int g_cnt_user[NU];
__device__ int g_cnt_song[NS];
__device__ int g_off_user[NU];   // inclusive scan of counts
__device__ int g_off_song[NS];
__device__ int g_cur_user[NU];   // bin cursors
__device__ int g_cur_song[NS];
__device__ int g_srt_us[NE];     // src ids of us edges, sorted by dst (song)
__device__ int g_srt_su[NE];     // src ids of su edges, sorted by dst (user)
__device__ int g_part[256];      // scan partials (shared by both scans)

// ---------------- packed f32x2 helpers --------------------------------------
__device__ __forceinline__ unsigned long long pack2(float lo, float hi) {
    unsigned long long r;
    asm("mov.b64 %0, {%1, %2};" : "=l"(r) : "f"(lo), "f"(hi));
    return r;
}
__device__ __forceinline__ void unpack2(unsigned long long v, float& lo, float& hi) {
    asm("mov.b64 {%0, %1}, %2;" : "=f"(lo), "=f"(hi) : "l"(v));
}
__device__ __forceinline__ unsigned long long ffma2(unsigned long long a,
                                                    unsigned long long b,
                                                    unsigned long long c) {
    unsigned long long d;
    asm("fma.rn.f32x2 %0, %1, %2, %3;" : "=l"(d) : "l"(a), "l"(b), "l"(c));
    return d;
}

// ---------------- CSR build kernels -----------------------------------------
__global__ void zero_int2(int* a, int na, int* b, int nb) {
    int i = blockIdx.x * blockDim.x + threadIdx.x;
    if (i < na) a[i] = 0;
    if (i < nb) b[i] = 0;
}

__global__ void count_kernel(const int* __restrict__ us_dst,
                             const int* __restrict__ su_dst,
                             int* __restrict__ cnt_song,
                             int* __restrict__ cnt_user, int n) {
    int i = blockIdx.x * blockDim.x + threadIdx.x;
    if (i < n) {
        atomicAdd(&cnt_song[us_dst[i]], 1);
        atomicAdd(&cnt_user[su_dst[i]], 1);
    }
}

// inclusive per-block scan (1024 elems/block); writes block totals to partials
__global__ void scan_block(const int* __restrict__ in, int* __restrict__ out,
                           int* __restrict__ partials, int n) {
    __shared__ int s[1024];
    int gid = blockIdx.x * 1024 + threadIdx.x;
    s[threadIdx.x] = (gid < n) ? in[gid] : 0;
    __syncthreads();
#pragma unroll
    for (int d = 1; d < 1024; d <<= 1) {
        int t = (threadIdx.x >= d) ? s[threadIdx.x - d] : 0;
        __syncthreads();
        s[threadIdx.x] += t;
        __syncthreads();
    }
    if (gid < n) out[gid] = s[threadIdx.x];
    if (threadIdx.x == 1023) partials[blockIdx.x] = s[1023];
}

// single-block inclusive scan of partials (nb <= 128)
__global__ void scan_partials(int* p, int nb) {
    __shared__ int s[128];
    s[threadIdx.x] = (threadIdx.x < nb) ? p[threadIdx.x] : 0;
    __syncthreads();
#pragma unroll
    for (int d = 1; d < 128; d <<= 1) {
        int t = (threadIdx.x >= d) ? s[threadIdx.x - d] : 0;
        __syncthreads();
        s[threadIdx.x] += t;
        __syncthreads();
    }
    if (threadIdx.x < nb) p[threadIdx.x] = s[threadIdx.x];
}

__global__ void scan_add(int* out, const int* __restrict__ partials, int n) {
    int gid = blockIdx.x * blockDim.x + threadIdx.x;
    if (gid < n) {
        int b = gid >> 10;
        if (b > 0) out[gid] += partials[b - 1];
    }
}

__global__ void cursor_init(const int* __restrict__ off_inc, int* __restrict__ cur,
                            int n) {
    int i = blockIdx.x * blockDim.x + threadIdx.x;
    if (i < n) cur[i] = (i > 0) ? off_inc[i - 1] : 0;
}

__global__ void bin_kernel(const int* __restrict__ src,
                           const int* __restrict__ dst, int* __restrict__ cur,
                           int* __restrict__ srt, int n) {
    int i = blockIdx.x * blockDim.x + threadIdx.x;
    if (i < n) {
        int pos = atomicAdd(&cur[dst[i]], 1);
        srt[pos] = src[i];
    }
}

// ---------------- gather-mean (one warp per destination node) ---------------
__global__ void gather_mean(const float* __restrict__ feat,
                            const int* __restrict__ srt,
                            const int* __restrict__ off_inc,
                            float* __restrict__ mean, int n) {
    int d = blockIdx.x * 8 + (threadIdx.x >> 5);
    if (d >= n) return;
    int lane = threadIdx.x & 31;
    int start = (d > 0) ? off_inc[d - 1] : 0;
    int end = off_inc[d];
    float4 acc = make_float4(0.f, 0.f, 0.f, 0.f);
    int i = start;
    for (; i + 2 <= end; i += 2) {
        int s0 = srt[i];
        int s1 = srt[i + 1];
        float4 a =
            *reinterpret_cast<const float4*>(feat + (size_t)s0 * DIN + lane * 4);
        float4 b =
            *reinterpret_cast<const float4*>(feat + (size_t)s1 * DIN + lane * 4);
        acc.x += a.x + b.x;
        acc.y += a.y + b.y;
        acc.z += a.z + b.z;
        acc.w += a.w + b.w;
    }
    if (i < end) {
        int s0 = srt[i];
        float4 a =
            *reinterpret_cast<const float4*>(feat + (size_t)s0 * DIN + lane * 4);
        acc.x += a.x;
        acc.y += a.y;
        acc.z += a.z;
        acc.w += a.w;
    }
    int deg = end - start;
    float inv = 1.0f / (float)((deg > 0) ? deg : 1);
    acc.x *= inv;
    acc.y *= inv;
    acc.z *= inv;
    acc.w *= inv;
    *reinterpret_cast<float4*>(mean + (size_t)d * DIN + lane * 4) = acc;
}

// ---------------- fused SAGE GEMM -------------------------------------------
// out[r,:] = relu?( xdst[r,:] @ Ws + mean[r,:] @ Wn + bias )
// K=128 each operand. Thread tile: 8 rows (4 f32x2 pairs) x 8 cols. FMA-bound.
template <int NOUT>
__global__ void __launch_bounds__(256) sage_gemm(
    const float* __restrict__ xdst, const float* __restrict__ mean,
    const float* __restrict__ Ws, const float* __restrict__ Wn,
    const float* __restrict__ bias, float* __restrict__ out, int M,
    int do_relu) {
    constexpr int NC = 8;            // cols per thread
    constexpr int CG = NOUT / NC;    // column groups: 16 (H1) / 8 (H2)
    constexpr int RG = 256 / CG;     // row groups: 16 / 32
    constexpr int TM = 8;            // rows per thread
    constexpr int NP = TM / 2;       // f32x2 row pairs
    constexpr int BM = RG * TM;      // 128 / 256
    constexpr int BK = 16;
    constexpr int XS = BM + 2;       // conflict-free stride

    __shared__ __align__(16) float sW[BK][NOUT];
    __shared__ __align__(16) float sX[BK][XS];

    const int tid = threadIdx.x;
    const int row0 = blockIdx.x * BM;
    const int cg = tid % CG;
    const int rg = tid / CG;
    const int n0 = cg * NC;
    const int r0 = rg * TM;

    unsigned long long acc[NP][NC];
#pragma unroll
    for (int i = 0; i < NP; i++)
#pragma unroll
        for (int j = 0; j < NC; j++) acc[i][j] = 0ull;

    for (int chunk = 0; chunk < 16; ++chunk) {
        const bool neigh = (chunk >= 8);
        const int kbase = (chunk & 7) * BK;
        const float* Wp = neigh ? Wn : Ws;
        const float* Xp = neigh ? mean : xdst;

        __syncthreads();
        // W chunk [BK x NOUT], vectorized
#pragma unroll
        for (int i = 0; i < (BK * NOUT) / (4 * 256); i++) {
            int idx = (tid + i * 256) * 4;
            int k = idx / NOUT, nn = idx % NOUT;
            *reinterpret_cast<float4*>(&sW[k][nn]) =
                *reinterpret_cast<const float4*>(&Wp[(size_t)(kbase + k) * NOUT + nn]);
        }
        // X chunk [BM x BK] transposed into sX[k][r], float4 along k
#pragma unroll
        for (int i = 0; i < (BM * BK) / (4 * 256); i++) {
            int idx = tid + i * 256;
            int r = idx / (BK / 4);
            int kq = idx % (BK / 4);
            int gr = row0 + r;
            float4 v = (gr < M) ? *reinterpret_cast<const float4*>(
                                      &Xp[(size_t)gr * DIN + kbase + kq * 4])
                                : make_float4(0.f, 0.f, 0.f, 0.f);
            sX[kq * 4 + 0][r] = v.x;
            sX[kq * 4 + 1][r] = v.y;
            sX[kq * 4 + 2][r] = v.z;
            sX[kq * 4 + 3][r] = v.w;
        }
        __syncthreads();

#pragma unroll
        for (int k = 0; k < BK; k++) {
            unsigned long long wd[NC];
#pragma unroll
            for (int j = 0; j < NC; j += 4) {
                float4 w = *reinterpret_cast<const float4*>(&sW[k][n0 + j]);
                wd[j + 0] = pack2(w.x, w.x);
                wd[j + 1] = pack2(w.y, w.y);
                wd[j + 2] = pack2(w.z, w.z);
                wd[j + 3] = pack2(w.w, w.w);
            }
#pragma unroll
            for (int i = 0; i < NP; i++) {
                unsigned long long xp =
                    *reinterpret_cast<const unsigned long long*>(
                        &sX[k][r0 + 2 * i]);
#pragma unroll
                for (int j = 0; j < NC; j++) acc[i][j] = ffma2(xp, wd[j], acc[i][j]);
            }
        }
    }

    // epilogue: bias (+relu), two rows per pair, 2x float4 stores per row
    float bv[NC];
#pragma unroll
    for (int j = 0; j < NC; j += 4) {
        float4 b = *reinterpret_cast<const float4*>(&bias[n0 + j]);
        bv[j] = b.x;
        bv[j + 1] = b.y;
        bv[j + 2] = b.z;
        bv[j + 3] = b.w;
    }
#pragma unroll
    for (int i = 0; i < NP; i++) {
        float la[NC], lb[NC];
#pragma unroll
        for (int j = 0; j < NC; j++) {
            unpack2(acc[i][j], la[j], lb[j]);
            la[j] += bv[j];
            lb[j] += bv[j];
            if (do_relu) {
                la[j] = fmaxf(la[j], 0.0f);
                lb[j] = fmaxf(lb[j], 0.0f);
            }
        }
        int ra = row0 + r0 + 2 * i;
        int rb = ra + 1;
        if (ra < M) {
            float* p = out + (size_t)ra * NOUT + n0;
            *reinterpret_cast<float4*>(p) = make_float4(la[0], la[1], la[2], la[3]);
            *reinterpret_cast<float4*>(p + 4) =
                make_float4(la[4], la[5], la[6], la[7]);
        }
        if (rb < M) {
            float* p = out + (size_t)rb * NOUT + n0;
            *reinterpret_cast<float4*>(p) = make_float4(lb[0], lb[1], lb[2], lb[3]);
            *reinterpret_cast<float4*>(p + 4) =
                make_float4(lb[4], lb[5], lb[6], lb[7]);
        }
    }
}

// ---------------- host launch -----------------------------------------------
extern "C" void kernel_launch(void* const* d_in, const int* in_sizes, int n_in,
                              void* d_out, int out_size) {
    const float* x_user = (const float*)d_in[0];
    const float* x_song = (const float*)d_in[1];
    const int* us_src = (const int*)d_in[2];
    const int* us_dst = (const int*)d_in[3];
    const int* su_src = (const int*)d_in[4];
    const int* su_dst = (const int*)d_in[5];
    const float* W1_us_n = (const float*)d_in[6];
    const float* W1_us_s = (const float*)d_in[7];
    const float* b1_us = (const float*)d_in[8];
    const float* W1_su_n = (const float*)d_in[9];
    const float* W1_su_s = (const float*)d_in[10];
    const float* b1_su = (const float*)d_in[11];
    const float* W2_us_n = (const float*)d_in[12];
    const float* W2_us_s = (const float*)d_in[13];
    const float* b2_us = (const float*)d_in[14];
    const float* W2_su_n = (const float*)d_in[15];
    const float* W2_su_s = (const float*)d_in[16];
    const float* b2_su = (const float*)d_in[17];
    float* out = (float*)d_out;

    float *mean_user, *mean_song, *h_user, *h_song;
    int *cnt_user, *cnt_song, *off_user, *off_song, *cur_user, *cur_song;
    int *srt_us, *srt_su, *part;
    cudaGetSymbolAddress((void**)&mean_user, g_mean_user);
    cudaGetSymbolAddress((void**)&mean_song, g_mean_song);
    cudaGetSymbolAddress((void**)&h_user, g_h_user);
    cudaGetSymbolAddress((void**)&h_song, g_h_song);
    cudaGetSymbolAddress((void**)&cnt_user, g_cnt_user);
    cudaGetSymbolAddress((void**)&cnt_song, g_cnt_song);
    cudaGetSymbolAddress((void**)&off_user, g_off_user);
    cudaGetSymbolAddress((void**)&off_song, g_off_song);
    cudaGetSymbolAddress((void**)&cur_user, g_cur_user);
    cudaGetSymbolAddress((void**)&cur_song, g_cur_song);
    cudaGetSymbolAddress((void**)&srt_us, g_srt_us);
    cudaGetSymbolAddress((void**)&srt_su, g_srt_su);
    cudaGetSymbolAddress((void**)&part, g_part);

    const int NB_S = (NS + 1023) / 1024;  // 49
    const int NB_U = (NU + 1023) / 1024;  // 98

    // ---- CSR build (counts -> scan -> bin), shared by both layers
    zero_int2<<<(NU + 255) / 256, 256>>>(cnt_user, NU, cnt_song, NS);
    count_kernel<<<(NE + 255) / 256, 256>>>(us_dst, su_dst, cnt_song, cnt_user, NE);

    scan_block<<<NB_S, 1024>>>(cnt_song, off_song, part, NS);
    scan_partials<<<1, 128>>>(part, NB_S);
    scan_add<<<(NS + 255) / 256, 256>>>(off_song, part, NS);

    scan_block<<<NB_U, 1024>>>(cnt_user, off_user, part, NU);
    scan_partials<<<1, 128>>>(part, NB_U);
    scan_add<<<(NU + 255) / 256, 256>>>(off_user, part, NU);

    cursor_init<<<(NS + 255) / 256, 256>>>(off_song, cur_song, NS);
    cursor_init<<<(NU + 255) / 256, 256>>>(off_user, cur_user, NU);
    bin_kernel<<<(NE + 255) / 256, 256>>>(us_src, us_dst, cur_song, srt_us, NE);
    bin_kernel<<<(NE + 255) / 256, 256>>>(su_src, su_dst, cur_user, srt_su, NE);

    // ---- layer 1: gather means, then fused GEMM (+bias+relu)
    gather_mean<<<(NS + 7) / 8, 256>>>(x_user, srt_us, off_song, mean_song, NS);
    gather_mean<<<(NU + 7) / 8, 256>>>(x_song, srt_su, off_user, mean_user, NU);

    sage_gemm<H1><<<(NS + 127) / 128, 256>>>(x_song, mean_song, W1_us_s, W1_us_n,
                                             b1_us, h_song, NS, 1);
    sage_gemm<H1><<<(NU + 127) / 128, 256>>>(x_user, mean_user, W1_su_s, W1_su_n,
                                             b1_su, h_user, NU, 1);

    // ---- layer 2: gather means of hidden, GEMM into concat output
    gather_mean<<<(NS + 7) / 8, 256>>>(h_user, srt_us, off_song, mean_song, NS);
    gather_mean<<<(NU + 7) / 8, 256>>>(h_song, srt_su, off_user, mean_user, NU);

    sage_gemm<H2><<<(NS + 255) / 256, 256>>>(h_song, mean_song, W2_us_s, W2_us_n,
                                             b2_us, out + (size_t)NU * H2, NS, 0);
    sage_gemm<H2><<<(NU + 255) / 256, 256>>>(h_user, mean_user, W2_su_s, W2_su_n,
                                             b2_su, out, NU, 0);
}

// round 4
// speedup vs baseline: 1.2114x; 1.0001x over previous
#include <cuda_runtime.h>
#include <cstdint>

#define NU 100000
#define NS 50000
#define NE 600000
#define DIN 128
#define H1 128
#define H2 64

// ---------------- scratch (device globals; no allocations allowed) ----------
__device__ float g_mean_user[NU * DIN];
__device__ float g_mean_song[NS * DIN];
__device__ float g_h_user[NU * H1];
__device__ float g_h_song[NS * H1];
__device__ int g_cnt_user[NU];
__device__ int g_cnt_song[NS];
__device__ int g_off_user[NU];   // inclusive scan of counts
__device__ int g_off_song[NS];
__device__ int g_cur_user[NU];   // bin cursors
__device__ int g_cur_song[NS];
__device__ int g_srt_us[NE];     // src ids of us edges, sorted by dst (song)
__device__ int g_srt_su[NE];     // src ids of su edges, sorted by dst (user)
__device__ int g_part[256];      // scan partials (shared by both scans)

// ---------------- packed f32x2 helpers --------------------------------------
__device__ __forceinline__ unsigned long long pack2(float lo, float hi) {
    unsigned long long r;
    asm("mov.b64 %0, {%1, %2};" : "=l"(r) : "f"(lo), "f"(hi));
    return r;
}
__device__ __forceinline__ void unpack2(unsigned long long v, float& lo, float& hi) {
    asm("mov.b64 {%0, %1}, %2;" : "=f"(lo), "=f"(hi) : "l"(v));
}
__device__ __forceinline__ unsigned long long ffma2(unsigned long long a,
                                                    unsigned long long b,
                                                    unsigned long long c) {
    unsigned long long d;
    asm("fma.rn.f32x2 %0, %1, %2, %3;" : "=l"(d) : "l"(a), "l"(b), "l"(c));
    return d;
}

// ---------------- CSR build kernels -----------------------------------------
__global__ void zero_int2(int* a, int na, int* b, int nb) {
    int i = blockIdx.x * blockDim.x + threadIdx.x;
    if (i < na) a[i] = 0;
    if (i < nb) b[i] = 0;
}

__global__ void count_kernel(const int* __restrict__ us_dst,
                             const int* __restrict__ su_dst,
                             int* __restrict__ cnt_song,
                             int* __restrict__ cnt_user, int n) {
    int i = blockIdx.x * blockDim.x + threadIdx.x;
    if (i < n) {
        atomicAdd(&cnt_song[us_dst[i]], 1);
        atomicAdd(&cnt_user[su_dst[i]], 1);
    }
}

// inclusive per-block scan (1024 elems/block); writes block totals to partials
__global__ void scan_block(const int* __restrict__ in, int* __restrict__ out,
                           int* __restrict__ partials, int n) {
    __shared__ int s[1024];
    int gid = blockIdx.x * 1024 + threadIdx.x;
    s[threadIdx.x] = (gid < n) ? in[gid] : 0;
    __syncthreads();
#pragma unroll
    for (int d = 1; d < 1024; d <<= 1) {
        int t = (threadIdx.x >= d) ? s[threadIdx.x - d] : 0;
        __syncthreads();
        s[threadIdx.x] += t;
        __syncthreads();
    }
    if (gid < n) out[gid] = s[threadIdx.x];
    if (threadIdx.x == 1023) partials[blockIdx.x] = s[1023];
}

// single-block inclusive scan of partials (nb <= 128)
__global__ void scan_partials(int* p, int nb) {
    __shared__ int s[128];
    s[threadIdx.x] = (threadIdx.x < nb) ? p[threadIdx.x] : 0;
    __syncthreads();
#pragma unroll
    for (int d = 1; d < 128; d <<= 1) {
        int t = (threadIdx.x >= d) ? s[threadIdx.x - d] : 0;
        __syncthreads();
        s[threadIdx.x] += t;
        __syncthreads();
    }
    if (threadIdx.x < nb) p[threadIdx.x] = s[threadIdx.x];
}

__global__ void scan_add(int* out, const int* __restrict__ partials, int n) {
    int gid = blockIdx.x * blockDim.x + threadIdx.x;
    if (gid < n) {
        int b = gid >> 10;
        if (b > 0) out[gid] += partials[b - 1];
    }
}

__global__ void cursor_init(const int* __restrict__ off_inc, int* __restrict__ cur,
                            int n) {
    int i = blockIdx.x * blockDim.x + threadIdx.x;
    if (i < n) cur[i] = (i > 0) ? off_inc[i - 1] : 0;
}

__global__ void bin_kernel(const int* __restrict__ src,
                           const int* __restrict__ dst, int* __restrict__ cur,
                           int* __restrict__ srt, int n) {
    int i = blockIdx.x * blockDim.x + threadIdx.x;
    if (i < n) {
        int pos = atomicAdd(&cur[dst[i]], 1);
        srt[pos] = src[i];
    }
}

// ---------------- gather-mean (one warp per destination node) ---------------
__global__ void gather_mean(const float* __restrict__ feat,
                            const int* __restrict__ srt,
                            const int* __restrict__ off_inc,
                            float* __restrict__ mean, int n) {
    int d = blockIdx.x * 8 + (threadIdx.x >> 5);
    if (d >= n) return;
    int lane = threadIdx.x & 31;
    int start = (d > 0) ? off_inc[d - 1] : 0;
    int end = off_inc[d];
    float4 acc = make_float4(0.f, 0.f, 0.f, 0.f);
    int i = start;
    for (; i + 2 <= end; i += 2) {
        int s0 = srt[i];
        int s1 = srt[i + 1];
        float4 a =
            *reinterpret_cast<const float4*>(feat + (size_t)s0 * DIN + lane * 4);
        float4 b =
            *reinterpret_cast<const float4*>(feat + (size_t)s1 * DIN + lane * 4);
        acc.x += a.x + b.x;
        acc.y += a.y + b.y;
        acc.z += a.z + b.z;
        acc.w += a.w + b.w;
    }
    if (i < end) {
        int s0 = srt[i];
        float4 a =
            *reinterpret_cast<const float4*>(feat + (size_t)s0 * DIN + lane * 4);
        acc.x += a.x;
        acc.y += a.y;
        acc.z += a.z;
        acc.w += a.w;
    }
    int deg = end - start;
    float inv = 1.0f / (float)((deg > 0) ? deg : 1);
    acc.x *= inv;
    acc.y *= inv;
    acc.z *= inv;
    acc.w *= inv;
    *reinterpret_cast<float4*>(mean + (size_t)d * DIN + lane * 4) = acc;
}

// ---------------- fused SAGE GEMM -------------------------------------------
// out[r,:] = relu?( xdst[r,:] @ Ws + mean[r,:] @ Wn + bias )
// K=128 each operand. Thread tile: 8 rows (4 f32x2 pairs) x 8 cols. FMA-bound.
template <int NOUT>
__global__ void __launch_bounds__(256) sage_gemm(
    const float* __restrict__ xdst, const float* __restrict__ mean,
    const float* __restrict__ Ws, const float* __restrict__ Wn,
    const float* __restrict__ bias, float* __restrict__ out, int M,
    int do_relu) {
    constexpr int NC = 8;            // cols per thread
    constexpr int CG = NOUT / NC;    // column groups: 16 (H1) / 8 (H2)
    constexpr int RG = 256 / CG;     // row groups: 16 / 32
    constexpr int TM = 8;            // rows per thread
    constexpr int NP = TM / 2;       // f32x2 row pairs
    constexpr int BM = RG * TM;      // 128 / 256
    constexpr int BK = 16;
    constexpr int XS = BM + 2;       // conflict-free stride

    __shared__ __align__(16) float sW[BK][NOUT];
    __shared__ __align__(16) float sX[BK][XS];

    const int tid = threadIdx.x;
    const int row0 = blockIdx.x * BM;
    const int cg = tid % CG;
    const int rg = tid / CG;
    const int n0 = cg * NC;
    const int r0 = rg * TM;

    unsigned long long acc[NP][NC];
#pragma unroll
    for (int i = 0; i < NP; i++)
#pragma unroll
        for (int j = 0; j < NC; j++) acc[i][j] = 0ull;

    for (int chunk = 0; chunk < 16; ++chunk) {
        const bool neigh = (chunk >= 8);
        const int kbase = (chunk & 7) * BK;
        const float* Wp = neigh ? Wn : Ws;
        const float* Xp = neigh ? mean : xdst;

        __syncthreads();
        // W chunk [BK x NOUT], vectorized
#pragma unroll
        for (int i = 0; i < (BK * NOUT) / (4 * 256); i++) {
            int idx = (tid + i * 256) * 4;
            int k = idx / NOUT, nn = idx % NOUT;
            *reinterpret_cast<float4*>(&sW[k][nn]) =
                *reinterpret_cast<const float4*>(&Wp[(size_t)(kbase + k) * NOUT + nn]);
        }
        // X chunk [BM x BK] transposed into sX[k][r], float4 along k
#pragma unroll
        for (int i = 0; i < (BM * BK) / (4 * 256); i++) {
            int idx = tid + i * 256;
            int r = idx / (BK / 4);
            int kq = idx % (BK / 4);
            int gr = row0 + r;
            float4 v = (gr < M) ? *reinterpret_cast<const float4*>(
                                      &Xp[(size_t)gr * DIN + kbase + kq * 4])
                                : make_float4(0.f, 0.f, 0.f, 0.f);
            sX[kq * 4 + 0][r] = v.x;
            sX[kq * 4 + 1][r] = v.y;
            sX[kq * 4 + 2][r] = v.z;
            sX[kq * 4 + 3][r] = v.w;
        }
        __syncthreads();

#pragma unroll
        for (int k = 0; k < BK; k++) {
            unsigned long long wd[NC];
#pragma unroll
            for (int j = 0; j < NC; j += 4) {
                float4 w = *reinterpret_cast<const float4*>(&sW[k][n0 + j]);
                wd[j + 0] = pack2(w.x, w.x);
                wd[j + 1] = pack2(w.y, w.y);
                wd[j + 2] = pack2(w.z, w.z);
                wd[j + 3] = pack2(w.w, w.w);
            }
#pragma unroll
            for (int i = 0; i < NP; i++) {
                unsigned long long xp =
                    *reinterpret_cast<const unsigned long long*>(
                        &sX[k][r0 + 2 * i]);
#pragma unroll
                for (int j = 0; j < NC; j++) acc[i][j] = ffma2(xp, wd[j], acc[i][j]);
            }
        }
    }

    // epilogue: bias (+relu), two rows per pair, 2x float4 stores per row
    float bv[NC];
#pragma unroll
    for (int j = 0; j < NC; j += 4) {
        float4 b = *reinterpret_cast<const float4*>(&bias[n0 + j]);
        bv[j] = b.x;
        bv[j + 1] = b.y;
        bv[j + 2] = b.z;
        bv[j + 3] = b.w;
    }
#pragma unroll
    for (int i = 0; i < NP; i++) {
        float la[NC], lb[NC];
#pragma unroll
        for (int j = 0; j < NC; j++) {
            unpack2(acc[i][j], la[j], lb[j]);
            la[j] += bv[j];
            lb[j] += bv[j];
            if (do_relu) {
                la[j] = fmaxf(la[j], 0.0f);
                lb[j] = fmaxf(lb[j], 0.0f);
            }
        }
        int ra = row0 + r0 + 2 * i;
        int rb = ra + 1;
        if (ra < M) {
            float* p = out + (size_t)ra * NOUT + n0;
            *reinterpret_cast<float4*>(p) = make_float4(la[0], la[1], la[2], la[3]);
            *reinterpret_cast<float4*>(p + 4) =
                make_float4(la[4], la[5], la[6], la[7]);
        }
        if (rb < M) {
            float* p = out + (size_t)rb * NOUT + n0;
            *reinterpret_cast<float4*>(p) = make_float4(lb[0], lb[1], lb[2], lb[3]);
            *reinterpret_cast<float4*>(p + 4) =
                make_float4(lb[4], lb[5], lb[6], lb[7]);
        }
    }
}

// ---------------- host launch -----------------------------------------------
extern "C" void kernel_launch(void* const* d_in, const int* in_sizes, int n_in,
                              void* d_out, int out_size) {
    const float* x_user = (const float*)d_in[0];
    const float* x_song = (const float*)d_in[1];
    const int* us_src = (const int*)d_in[2];
    const int* us_dst = (const int*)d_in[3];
    const int* su_src = (const int*)d_in[4];
    const int* su_dst = (const int*)d_in[5];
    const float* W1_us_n = (const float*)d_in[6];
    const float* W1_us_s = (const float*)d_in[7];
    const float* b1_us = (const float*)d_in[8];
    const float* W1_su_n = (const float*)d_in[9];
    const float* W1_su_s = (const float*)d_in[10];
    const float* b1_su = (const float*)d_in[11];
    const float* W2_us_n = (const float*)d_in[12];
    const float* W2_us_s = (const float*)d_in[13];
    const float* b2_us = (const float*)d_in[14];
    const float* W2_su_n = (const float*)d_in[15];
    const float* W2_su_s = (const float*)d_in[16];
    const float* b2_su = (const float*)d_in[17];
    float* out = (float*)d_out;

    float *mean_user, *mean_song, *h_user, *h_song;
    int *cnt_user, *cnt_song, *off_user, *off_song, *cur_user, *cur_song;
    int *srt_us, *srt_su, *part;
    cudaGetSymbolAddress((void**)&mean_user, g_mean_user);
    cudaGetSymbolAddress((void**)&mean_song, g_mean_song);
    cudaGetSymbolAddress((void**)&h_user, g_h_user);
    cudaGetSymbolAddress((void**)&h_song, g_h_song);
    cudaGetSymbolAddress((void**)&cnt_user, g_cnt_user);
    cudaGetSymbolAddress((void**)&cnt_song, g_cnt_song);
    cudaGetSymbolAddress((void**)&off_user, g_off_user);
    cudaGetSymbolAddress((void**)&off_song, g_off_song);
    cudaGetSymbolAddress((void**)&cur_user, g_cur_user);
    cudaGetSymbolAddress((void**)&cur_song, g_cur_song);
    cudaGetSymbolAddress((void**)&srt_us, g_srt_us);
    cudaGetSymbolAddress((void**)&srt_su, g_srt_su);
    cudaGetSymbolAddress((void**)&part, g_part);

    const int NB_S = (NS + 1023) / 1024;  // 49
    const int NB_U = (NU + 1023) / 1024;  // 98

    // ---- CSR build (counts -> scan -> bin), shared by both layers
    zero_int2<<<(NU + 255) / 256, 256>>>(cnt_user, NU, cnt_song, NS);
    count_kernel<<<(NE + 255) / 256, 256>>>(us_dst, su_dst, cnt_song, cnt_user, NE);

    scan_block<<<NB_S, 1024>>>(cnt_song, off_song, part, NS);
    scan_partials<<<1, 128>>>(part, NB_S);
    scan_add<<<(NS + 255) / 256, 256>>>(off_song, part, NS);

    scan_block<<<NB_U, 1024>>>(cnt_user, off_user, part, NU);
    scan_partials<<<1, 128>>>(part, NB_U);
    scan_add<<<(NU + 255) / 256, 256>>>(off_user, part, NU);

    cursor_init<<<(NS + 255) / 256, 256>>>(off_song, cur_song, NS);
    cursor_init<<<(NU + 255) / 256, 256>>>(off_user, cur_user, NU);
    bin_kernel<<<(NE + 255) / 256, 256>>>(us_src, us_dst, cur_song, srt_us, NE);
    bin_kernel<<<(NE + 255) / 256, 256>>>(su_src, su_dst, cur_user, srt_su, NE);

    // ---- layer 1: gather means, then fused GEMM (+bias+relu)
    gather_mean<<<(NS + 7) / 8, 256>>>(x_user, srt_us, off_song, mean_song, NS);
    gather_mean<<<(NU + 7) / 8, 256>>>(x_song, srt_su, off_user, mean_user, NU);

    sage_gemm<H1><<<(NS + 127) / 128, 256>>>(x_song, mean_song, W1_us_s, W1_us_n,
                                             b1_us, h_song, NS, 1);
    sage_gemm<H1><<<(NU + 127) / 128, 256>>>(x_user, mean_user, W1_su_s, W1_su_n,
                                             b1_su, h_user, NU, 1);

    // ---- layer 2: gather means of hidden, GEMM into concat output
    gather_mean<<<(NS + 7) / 8, 256>>>(h_user, srt_us, off_song, mean_song, NS);
    gather_mean<<<(NU + 7) / 8, 256>>>(h_song, srt_su, off_user, mean_user, NU);

    sage_gemm<H2><<<(NS + 255) / 256, 256>>>(h_song, mean_song, W2_us_s, W2_us_n,
                                             b2_us, out + (size_t)NU * H2, NS, 0);
    sage_gemm<H2><<<(NU + 255) / 256, 256>>>(h_user, mean_user, W2_su_s, W2_su_n,
                                             b2_su, out, NU, 0);
}